// round 4
// baseline (speedup 1.0000x reference)
#include <cuda_runtime.h>

// ---------------------------------------------------------------------------
// HGTransformerLayer — fp32, edge-type factorized (t in {0,1}).
//   k[b,n] = Kbase[n] + KE[t],  v[b,n] = Vbase[n] + VE[t]
// scores[b,h,n] = Qs[b,h].Kbase[n,h] + qe[b,h,t];  out adds w0*VE0 + w1*VE1.
// f32x2 (FFMA2) everywhere; attn CTA = 512 threads / 16 warps (RF-friendly).
// ---------------------------------------------------------------------------

#define SCALE_Q 0.17677669529663687f  // 1/sqrt(32)

typedef unsigned long long ull;

// scratch (no allocations allowed)
__device__ float g_Q[1024 * 256];   // [h][b][32], scaled
__device__ float g_K[1024 * 256];   // [h][n][32]
__device__ float g_V[1024 * 256];   // [h][n][32]
__device__ float g_KE[2 * 256];
__device__ float g_VE[2 * 256];
__device__ float g_AO[1024 * 256];  // row-major [b][256]
__device__ unsigned g_mba[1024 * 2 * 32];  // adjacency bitmask [(row*2+half)*32 + lane]
__device__ unsigned g_mbt[1024 * 2 * 32];  // edge-type bitmask

#define FMA2(acc, a, b) \
    asm("fma.rn.f32x2 %0, %1, %2, %3;" : "=l"(acc) : "l"(a), "l"(b), "l"(acc))

__device__ __forceinline__ ull bcast2(float x) {
    ull r;
    asm("mov.b64 %0, {%1, %1};" : "=l"(r) : "f"(x));
    return r;
}
__device__ __forceinline__ float2 unpack2(ull v) {
    float2 f;
    asm("mov.b64 {%0, %1}, %2;" : "=f"(f.x), "=f"(f.y) : "l"(v));
    return f;
}

// ---------------------------------------------------------------------------
// fp32 GEMM: C = (A[M,256] @ W[256,256]^T + bias) * scale
// BM=32, BN=64, BK=16, 128 threads, 4x4 tile (f32x2 inner), reg double-buffer.
// ---------------------------------------------------------------------------
__device__ __forceinline__ void gemm_body(const float* __restrict__ A,
                                          const float* __restrict__ W,
                                          const float* __restrict__ bias,
                                          float* __restrict__ C, float scale,
                                          bool headmode)
{
    __shared__ float As[16][36];
    __shared__ float Ws[16][68];

    const int tid = threadIdx.x;
    const int m0 = blockIdx.x * 32;
    const int n0 = blockIdx.y * 64;
    const int tx = tid & 15;
    const int ty = tid >> 4;
    const int am = tid >> 2, ak = tid & 3;

    float4 ra  = *reinterpret_cast<const float4*>(&A[(m0 + am) * 256 + ak * 4]);
    float4 rw0 = *reinterpret_cast<const float4*>(&W[(n0 + am) * 256 + ak * 4]);
    float4 rw1 = *reinterpret_cast<const float4*>(&W[(n0 + am + 32) * 256 + ak * 4]);

    ull acc2[4][2];
#pragma unroll
    for (int i = 0; i < 4; ++i) { acc2[i][0] = 0ull; acc2[i][1] = 0ull; }

    for (int k0 = 0; k0 < 256; k0 += 16) {
        As[ak * 4 + 0][am] = ra.x; As[ak * 4 + 1][am] = ra.y;
        As[ak * 4 + 2][am] = ra.z; As[ak * 4 + 3][am] = ra.w;
        Ws[ak * 4 + 0][am] = rw0.x; Ws[ak * 4 + 1][am] = rw0.y;
        Ws[ak * 4 + 2][am] = rw0.z; Ws[ak * 4 + 3][am] = rw0.w;
        Ws[ak * 4 + 0][am + 32] = rw1.x; Ws[ak * 4 + 1][am + 32] = rw1.y;
        Ws[ak * 4 + 2][am + 32] = rw1.z; Ws[ak * 4 + 3][am + 32] = rw1.w;
        __syncthreads();
        if (k0 + 16 < 256) {
            ra  = *reinterpret_cast<const float4*>(&A[(m0 + am) * 256 + k0 + 16 + ak * 4]);
            rw0 = *reinterpret_cast<const float4*>(&W[(n0 + am) * 256 + k0 + 16 + ak * 4]);
            rw1 = *reinterpret_cast<const float4*>(&W[(n0 + am + 32) * 256 + k0 + 16 + ak * 4]);
        }
#pragma unroll
        for (int k = 0; k < 16; ++k) {
            float4 a4 = *reinterpret_cast<const float4*>(&As[k][ty * 4]);
            const ull* wp = reinterpret_cast<const ull*>(&Ws[k][tx * 4]);
            ull w20 = wp[0], w21 = wp[1];
            ull au0 = bcast2(a4.x), au1 = bcast2(a4.y);
            ull au2 = bcast2(a4.z), au3 = bcast2(a4.w);
            FMA2(acc2[0][0], au0, w20); FMA2(acc2[0][1], au0, w21);
            FMA2(acc2[1][0], au1, w20); FMA2(acc2[1][1], au1, w21);
            FMA2(acc2[2][0], au2, w20); FMA2(acc2[2][1], au2, w21);
            FMA2(acc2[3][0], au3, w20); FMA2(acc2[3][1], au3, w21);
        }
        __syncthreads();
    }
#pragma unroll
    for (int i = 0; i < 4; ++i) {
        int m = m0 + ty * 4 + i;
#pragma unroll
        for (int jp = 0; jp < 2; ++jp) {
            float2 f = unpack2(acc2[i][jp]);
            int n = n0 + tx * 4 + jp * 2;
            float v0 = (f.x + bias[n]) * scale;
            float v1 = (f.y + bias[n + 1]) * scale;
            if (headmode) {
                C[(n >> 5) * 32768 + m * 32 + (n & 31)] = v0;
                C[((n + 1) >> 5) * 32768 + m * 32 + ((n + 1) & 31)] = v1;
            } else {
                C[m * 256 + n] = v0;
                C[m * 256 + n + 1] = v1;
            }
        }
    }
}

__global__ void qkv_kernel(const float* __restrict__ hT, const float* __restrict__ hN,
                           const float* __restrict__ Wq, const float* __restrict__ bq,
                           const float* __restrict__ Wk, const float* __restrict__ bk,
                           const float* __restrict__ Wv, const float* __restrict__ bv)
{
    if (blockIdx.z == 0)      gemm_body(hT, Wq, bq, g_Q, SCALE_Q, true);
    else if (blockIdx.z == 1) gemm_body(hN, Wk, bk, g_K, 1.f, true);
    else                      gemm_body(hN, Wv, bv, g_V, 1.f, true);
}

__global__ void proj_kernel(const float* __restrict__ Wo, const float* __restrict__ bo,
                            float* __restrict__ out)
{
    gemm_body(g_AO, Wo, bo, out, 1.f, false);
}

// KE[t] = E[t]@Wk^T, VE[t] = E[t]@Wv^T
__global__ void edge_kernel(const float* __restrict__ E, const float* __restrict__ Wk,
                            const float* __restrict__ Wv)
{
    const int t = blockIdx.x & 1;
    const int isv = blockIdx.x >> 1;
    const float* W = isv ? Wv : Wk;
    float* out = isv ? g_VE : g_KE;

    __shared__ float e[256];
    e[threadIdx.x] = E[t * 256 + threadIdx.x];
    __syncthreads();

    const int warp = threadIdx.x >> 5, lane = threadIdx.x & 31;
    for (int d = warp; d < 256; d += 8) {
        float acc = 0.f;
        for (int k = lane; k < 256; k += 32) acc += e[k] * W[d * 256 + k];
#pragma unroll
        for (int m = 16; m; m >>= 1) acc += __shfl_xor_sync(0xffffffffu, acc, m);
        if (lane == 0) out[t * 256 + d] = acc;
    }
}

// pack adj/et into per-(row,half,lane) 16-bit masks (bit ii = n = half*512+lane+32*ii)
__global__ void pack_kernel(const int* __restrict__ adj, const int* __restrict__ et)
{
    const int unit = blockIdx.x * 8 + (threadIdx.x >> 5);  // (row*2 + half)
    const int l = threadIdx.x & 31;
    const int row = unit >> 1, half = unit & 1;
    const int* ap = adj + row * 1024 + half * 512 + l;
    const int* tp = et  + row * 1024 + half * 512 + l;
    unsigned va = 0, vt = 0;
#pragma unroll
    for (int ii = 0; ii < 16; ++ii) {
        if (ap[ii * 32]) va |= 1u << ii;
        if (tp[ii * 32]) vt |= 1u << ii;
    }
    g_mba[unit * 32 + l] = va;
    g_mbt[unit * 32 + l] = vt;
}

// ---------------------------------------------------------------------------
// Fused attention: grid (64 row-tiles, 8 heads), 512 threads / 16 warps.
// warp w: rp = w&7 -> rows {2rp, 2rp+1}; half = w>>3 -> n range of 512.
// lane l: n = half*512 + l + 32*ii, ii<16.
// K/V slice [1024][34] in smem, scores [16][1024] in smem,
// AV cross-thread reduction through the recycled K buffer (64 srcs, stride 513).
// ---------------------------------------------------------------------------
#define SK_F (1024 * 34)
#define SS_F (16 * 1024)
#define SQ_F (16 * 34)

__global__ __launch_bounds__(512, 1)
void attn_kernel()
{
    extern __shared__ float sm[];
    float* sK   = sm;                        // K, then V, then reduction (34816 f)
    float* sS   = sK + SK_F;                 // scores/attn (16384 f)
    float* sQ   = sS + SS_F;                 // [16][34]
    float* sqe  = sQ + SQ_F;                 // [16][2]
    float* sKE  = sqe + 32;                  // [2][32]
    float* sVE  = sKE + 64;                  // [2][32]
    float* smax = sVE + 64;                  // [16][2]
    float* ssum = smax + 32;                 // [16][2]
    float* sw1  = ssum + 32;                 // [16][2]

    const int tid = threadIdx.x;
    const int h = blockIdx.y;
    const int b0 = blockIdx.x << 4;
    const int l = tid & 31;
    const int w = tid >> 5;
    const int rp = w & 7;
    const int half = w >> 3;
    const int rbase = rp << 1;
    const int nb = half * 512 + l;

    // ---- load K slice (contiguous 128KB) + Q + edge vecs ----
    {
        const float4* src = reinterpret_cast<const float4*>(g_K + h * 32768);
#pragma unroll
        for (int it = 0; it < 16; ++it) {
            int idx = tid + (it << 9);
            float4 v = src[idx];
            float* p = &sK[(idx >> 3) * 34 + (idx & 7) * 4];
            p[0] = v.x; p[1] = v.y; p[2] = v.z; p[3] = v.w;
        }
    }
    {
        int row = tid >> 5, d = tid & 31;   // 512 threads cover [16][32]
        sQ[row * 34 + d] = g_Q[h * 32768 + (b0 + row) * 32 + d];
    }
    if (tid < 64) {
        int t = tid >> 5, d = tid & 31;
        sKE[tid] = g_KE[t * 256 + h * 32 + d];
        sVE[tid] = g_VE[t * 256 + h * 32 + d];
    }
    __syncthreads();

    // qe[row][t] = Q[row].KE[t]
    if (tid < 32) {
        int rr = tid >> 1, t = tid & 1;
        float a = 0.f;
#pragma unroll
        for (int d = 0; d < 32; ++d) a += sQ[rr * 34 + d] * sKE[t * 32 + d];
        sqe[rr * 2 + t] = a;
    }
    __syncthreads();

    // masks + qe + q into registers (2 rows per warp)
    unsigned vb[2], tb[2];
    float qe0[2], qe1[2];
    ull q2[2][16];
#pragma unroll
    for (int r = 0; r < 2; ++r) {
        int row = b0 + rbase + r;
        vb[r] = g_mba[(row * 2 + half) * 32 + l];
        tb[r] = g_mbt[(row * 2 + half) * 32 + l];
        qe0[r] = sqe[(rbase + r) * 2 + 0];
        qe1[r] = sqe[(rbase + r) * 2 + 1];
#pragma unroll
        for (int p = 0; p < 16; ++p)
            q2[r][p] = *reinterpret_cast<const ull*>(&sQ[(rbase + r) * 34 + 2 * p]);
    }

    // ---- scores ----
    float rmax[2] = {-3.0e38f, -3.0e38f};
#pragma unroll 2
    for (int ii = 0; ii < 16; ++ii) {
        int n = nb + (ii << 5);
        const float* kp = &sK[n * 34];
        ull a0 = 0, a1 = 0;
#pragma unroll
        for (int p = 0; p < 16; ++p) {
            ull kv = *reinterpret_cast<const ull*>(&kp[2 * p]);
            FMA2(a0, q2[0][p], kv);
            FMA2(a1, q2[1][p], kv);
        }
        float2 f0 = unpack2(a0), f1 = unpack2(a1);
        float s0 = f0.x + f0.y + (((tb[0] >> ii) & 1u) ? qe1[0] : qe0[0]);
        float s1 = f1.x + f1.y + (((tb[1] >> ii) & 1u) ? qe1[1] : qe0[1]);
        sS[(rbase + 0) * 1024 + n] = s0;
        sS[(rbase + 1) * 1024 + n] = s1;
        if ((vb[0] >> ii) & 1u) rmax[0] = fmaxf(rmax[0], s0);
        if ((vb[1] >> ii) & 1u) rmax[1] = fmaxf(rmax[1], s1);
    }
#pragma unroll
    for (int s = 16; s; s >>= 1) {
        rmax[0] = fmaxf(rmax[0], __shfl_xor_sync(0xffffffffu, rmax[0], s));
        rmax[1] = fmaxf(rmax[1], __shfl_xor_sync(0xffffffffu, rmax[1], s));
    }
    if (l == 0) {
        smax[(rbase + 0) * 2 + half] = rmax[0];
        smax[(rbase + 1) * 2 + half] = rmax[1];
    }
    __syncthreads();   // also: everyone done reading sK

    float rm[2];
#pragma unroll
    for (int r = 0; r < 2; ++r)
        rm[r] = fmaxf(smax[(rbase + r) * 2], smax[(rbase + r) * 2 + 1]);

    // ---- load V into sK (overlaps with exp pass below) ----
    {
        const float4* src = reinterpret_cast<const float4*>(g_V + h * 32768);
#pragma unroll
        for (int it = 0; it < 16; ++it) {
            int idx = tid + (it << 9);
            float4 v = src[idx];
            float* p = &sK[(idx >> 3) * 34 + (idx & 7) * 4];
            p[0] = v.x; p[1] = v.y; p[2] = v.z; p[3] = v.w;
        }
    }

    // ---- exp + row sums ----
    float rsum[2] = {0.f, 0.f};
    float rw1[2] = {0.f, 0.f};
#pragma unroll 2
    for (int ii = 0; ii < 16; ++ii) {
        int n = nb + (ii << 5);
#pragma unroll
        for (int r = 0; r < 2; ++r) {
            float s = sS[(rbase + r) * 1024 + n];
            float p = ((vb[r] >> ii) & 1u) ? __expf(s - rm[r]) : 0.f;
            sS[(rbase + r) * 1024 + n] = p;
            rsum[r] += p;
            if ((tb[r] >> ii) & 1u) rw1[r] += p;
        }
    }
#pragma unroll
    for (int s = 16; s; s >>= 1)
#pragma unroll
        for (int r = 0; r < 2; ++r) {
            rsum[r] += __shfl_xor_sync(0xffffffffu, rsum[r], s);
            rw1[r]  += __shfl_xor_sync(0xffffffffu, rw1[r], s);
        }
    if (l == 0)
#pragma unroll
        for (int r = 0; r < 2; ++r) {
            ssum[(rbase + r) * 2 + half] = rsum[r];
            sw1[(rbase + r) * 2 + half]  = rw1[r];
        }
    __syncthreads();   // V loaded, attn in sS, sums published

    float inv[2];
#pragma unroll
    for (int r = 0; r < 2; ++r) {
        float st = ssum[(rbase + r) * 2] + ssum[(rbase + r) * 2 + 1];
        inv[r] = st > 0.f ? 1.f / st : 0.f;
    }

    // ---- AV: acc[r][p] covers d = 2p, 2p+1 ----
    ull acc[2][16];
#pragma unroll
    for (int r = 0; r < 2; ++r)
#pragma unroll
        for (int p = 0; p < 16; ++p) acc[r][p] = 0ull;

#pragma unroll 2
    for (int ii = 0; ii < 16; ++ii) {
        int n = nb + (ii << 5);
        const float* vp = &sK[n * 34];
        ull ab0 = bcast2(sS[(rbase + 0) * 1024 + n] * inv[0]);
        ull ab1 = bcast2(sS[(rbase + 1) * 1024 + n] * inv[1]);
#pragma unroll
        for (int p = 0; p < 16; ++p) {
            ull vv = *reinterpret_cast<const ull*>(&vp[2 * p]);
            FMA2(acc[0][p], ab0, vv);
            FMA2(acc[1][p], ab1, vv);
        }
    }
    __syncthreads();   // all done reading V -> sK reusable as reduction buffer

    // ---- cross-thread reduction: red[src][out], stride 513 (conflict-free) ----
    {
        const int src = half * 32 + l;
#pragma unroll
        for (int r = 0; r < 2; ++r)
#pragma unroll
            for (int p = 0; p < 16; ++p) {
                float2 f = unpack2(acc[r][p]);
                int o = (rbase + r) * 32 + 2 * p;
                sK[src * 513 + o]     = f.x;
                sK[src * 513 + o + 1] = f.y;
            }
    }
    __syncthreads();

    {
        int o = tid;                    // 512 outputs, one per thread
        int row = o >> 5, d = o & 31;
        float a0 = 0.f, a1 = 0.f, a2 = 0.f, a3 = 0.f;
#pragma unroll
        for (int s = 0; s < 64; s += 4) {
            a0 += sK[(s + 0) * 513 + o];
            a1 += sK[(s + 1) * 513 + o];
            a2 += sK[(s + 2) * 513 + o];
            a3 += sK[(s + 3) * 513 + o];
        }
        float st = ssum[row * 2] + ssum[row * 2 + 1];
        float w1t = sw1[row * 2] + sw1[row * 2 + 1];
        float invT = st > 0.f ? 1.f / st : 0.f;
        float w1 = w1t * invT;
        float w0 = (st - w1t) * invT;
        float oval = a0 + a1 + a2 + a3 + w0 * sVE[d] + w1 * sVE[32 + d];
        g_AO[(b0 + row) * 256 + h * 32 + d] = oval;
    }
}

// ---------------------------------------------------------------------------
extern "C" void kernel_launch(void* const* d_in, const int* in_sizes, int n_in,
                              void* d_out, int out_size)
{
    const float* h_target = (const float*)d_in[0];
    const float* h_neigh  = (const float*)d_in[1];
    const int*   adjacency = (const int*)d_in[2];
    const int*   edge_types = (const int*)d_in[3];
    const float* Wq = (const float*)d_in[4];
    const float* bq = (const float*)d_in[5];
    const float* Wk = (const float*)d_in[6];
    const float* bk = (const float*)d_in[7];
    const float* Wv = (const float*)d_in[8];
    const float* bv = (const float*)d_in[9];
    const float* Wo = (const float*)d_in[10];
    const float* bo = (const float*)d_in[11];
    const float* E  = (const float*)d_in[12];
    float* out = (float*)d_out;

    const int attn_smem = (SK_F + SS_F + SQ_F + 32 + 64 + 64 + 32 + 32 + 32) * 4; // 208000 B
    static int smem_set = 0;
    if (!smem_set) {
        cudaFuncSetAttribute(attn_kernel, cudaFuncAttributeMaxDynamicSharedMemorySize,
                             attn_smem);
        smem_set = 1;
    }

    pack_kernel<<<256, 256>>>(adjacency, edge_types);
    qkv_kernel<<<dim3(32, 4, 3), 128>>>(h_target, h_neigh, Wq, bq, Wk, bk, Wv, bv);
    edge_kernel<<<4, 256>>>(E, Wk, Wv);
    attn_kernel<<<dim3(64, 8), 512, attn_smem>>>();
    proj_kernel<<<dim3(32, 4), 128>>>(Wo, bo, out);
}